// round 11
// baseline (speedup 1.0000x reference)
#include <cuda_runtime.h>
#include <cuda_fp16.h>
#include <cstdint>

// ===================== scratch (device globals; allocation-free) =====================
__device__ float g_s [4194304];   // [4,1024,1024] raw scores
__device__ float g_v [4194304];   // [4096,1024] V (fp32, pre-transpose)
__device__ float g_x1[4194304];   // x + attn proj (fp32, for gates + residual)
__device__ float g_g [32768];     // gates [E][4096]

// fp16 hi/lo pools (split-precision operands), element offsets below
#define OFF_X   0LL
#define OFF_Q   4194304LL
#define OFF_K   8388608LL
#define OFF_VT  12582912LL
#define OFF_P   16777216LL
#define OFF_A   20971520LL
#define OFF_X1  25165824LL
#define OFF_H   29360128LL
#define OFF_WQ  46137344LL
#define OFF_WK  47185920LL
#define OFF_WV  48234496LL
#define OFF_WO  49283072LL
#define OFF_W1  50331648LL
#define OFF_W2  83886080LL
#define POOL_SZ 117440512LL
__device__ __half g_hi[POOL_SZ];
__device__ __half g_lo[POOL_SZ];

// ===================== PTX helpers (sm_80+ only) =====================
__device__ __forceinline__ uint32_t s2u(const void* p) {
    uint32_t a;
    asm("{ .reg .u64 t; cvta.to.shared.u64 t, %1; cvt.u32.u64 %0, t; }" : "=r"(a) : "l"(p));
    return a;
}
__device__ __forceinline__ void ldsm4(uint32_t& r0, uint32_t& r1, uint32_t& r2, uint32_t& r3,
                                      uint32_t addr) {
    asm volatile("ldmatrix.sync.aligned.m8n8.x4.shared.b16 {%0,%1,%2,%3}, [%4];"
                 : "=r"(r0), "=r"(r1), "=r"(r2), "=r"(r3) : "r"(addr));
}
__device__ __forceinline__ void mma16816(float* d, const uint32_t* a, const uint32_t* b) {
    asm volatile(
        "mma.sync.aligned.m16n8k16.row.col.f32.f16.f16.f32 "
        "{%0,%1,%2,%3}, {%4,%5,%6,%7}, {%8,%9}, {%0,%1,%2,%3};"
        : "+f"(d[0]), "+f"(d[1]), "+f"(d[2]), "+f"(d[3])
        : "r"(a[0]), "r"(a[1]), "r"(a[2]), "r"(a[3]), "r"(b[0]), "r"(b[1]));
}
__device__ __forceinline__ void cpasync16(uint32_t saddr, const void* g) {
    asm volatile("cp.async.cg.shared.global [%0], [%1], 16;" :: "r"(saddr), "l"(g));
}
#define CP_COMMIT() asm volatile("cp.async.commit_group;" ::: "memory")
#define CP_WAIT0()  asm volatile("cp.async.wait_group 0;" ::: "memory")

// ===================== split-fp16 warp-MMA GEMM =====================
// Tile 128x128, K-chunk 64, double-buffered cp.async, 256 threads (8 warps 4m x 2n).
// TERMS==3: D = Ah*Bh + Ah*Bl + Al*Bh   (near-fp32)
// TERMS==2: D = Ah*Bh + Ah*Bl           (A unsplit fp16)
// TERMS==1: D = Ah*Bh                   (plain fp16; err ~2^-10 pre-aggregation)
#define KT 64
#define RP 72                    // padded row length (elements)
#define TILE_E (128 * RP)        // 9216 elems per operand tile

#define F_BIAS  1
#define F_RELU  2
#define F_RES   4
#define F_DUP   8
#define F_GACC  16
#define F_WF32  32
#define F_EMIT  64
#define F_EMITH 128

template <int FLAGS, int TERMS>
__global__ void __launch_bounds__(256, 1)
tgemm(const __half* __restrict__ Ahi, const __half* __restrict__ Alo,
      const __half* __restrict__ Bhi, const __half* __restrict__ Blo,
      const float* __restrict__ bias, const float* __restrict__ gate,
      const float* __restrict__ res, float* __restrict__ C, float* __restrict__ C2,
      __half* __restrict__ Ehi, __half* __restrict__ Elo,
      int M, int N, int K, long long bA, long long bB, long long bC) {
    constexpr int NTILES = TERMS + 1;  // 3:Ah,Al,Bh,Bl  2:Ah,Bh,Bl  1:Ah,Bh
    constexpr uint32_t STAGE_B = NTILES * TILE_E * 2;
    constexpr uint32_t BH_OFF = (TERMS == 3 ? 2 : 1) * TILE_E * 2;

    extern __shared__ __half sm[];
    const int tid = threadIdx.x, lane = tid & 31, wid = tid >> 5;
    const int wm = wid >> 1, wn = wid & 1;
    const long long z = blockIdx.z;
    const int m0 = blockIdx.y * 128, n0 = blockIdx.x * 128;
    const __half* Ah = Ahi + z * bA + (long long)m0 * K;
    const __half* Al = (TERMS == 3) ? (Alo + z * bA + (long long)m0 * K) : nullptr;
    const __half* Bh = Bhi + z * bB + (long long)n0 * K;
    const __half* Bl = (TERMS >= 2) ? (Blo + z * bB + (long long)n0 * K) : nullptr;
    const uint32_t sbase = s2u(sm);

    // loader mapping: thread -> (row, 32-elem half-row)
    const int lr = tid >> 1;
    const int lc0 = (tid & 1) * 32;
    const long long gro = (long long)lr * K + lc0;
    const uint32_t sro = (uint32_t)lr * RP * 2 + (uint32_t)lc0 * 2;

    auto load_stage = [&](int kt, int s) {
        const long long go = gro + (long long)kt * KT;
        const uint32_t sd = sbase + (uint32_t)s * STAGE_B + sro;
#pragma unroll
        for (int j = 0; j < 4; ++j) {
            cpasync16(sd + j * 16, Ah + go + j * 8);
            if (TERMS == 3) cpasync16(sd + TILE_E * 2 + j * 16, Al + go + j * 8);
            cpasync16(sd + BH_OFF + j * 16, Bh + go + j * 8);
            if (TERMS >= 2) cpasync16(sd + BH_OFF + TILE_E * 2 + j * 16, Bl + go + j * 8);
        }
    };

    // ldmatrix per-lane base addresses (byte offsets into a stage)
    const uint32_t aBase =
        sbase + ((uint32_t)(wm * 32 + (lane & 7) + ((lane >> 3) & 1) * 8) * RP +
                 ((lane >> 4) & 1) * 8) * 2;
    const uint32_t bBase =
        sbase + BH_OFF +
        ((uint32_t)(wn * 64 + (lane >> 4) * 8 + (lane & 7)) * RP + ((lane >> 3) & 1) * 8) * 2;

    float acc[2][8][4];
#pragma unroll
    for (int i = 0; i < 2; i++)
#pragma unroll
        for (int j = 0; j < 8; j++)
#pragma unroll
            for (int q = 0; q < 4; q++) acc[i][j][q] = 0.0f;

    load_stage(0, 0);
    CP_COMMIT();

    const int nk = K >> 6;
    for (int kt = 0; kt < nk; ++kt) {
        const int b = kt & 1;
        CP_WAIT0();
        __syncthreads();
        if (kt + 1 < nk) {
            load_stage(kt + 1, b ^ 1);
            CP_COMMIT();
        }
        const uint32_t st = (uint32_t)b * STAGE_B;
#pragma unroll
        for (int ks = 0; ks < 4; ++ks) {
            uint32_t ah[2][4], al[2][4], bh[8][2], bl[8][2];
#pragma unroll
            for (int mi = 0; mi < 2; ++mi) {
                const uint32_t ad = aBase + st + (uint32_t)(mi * 16 * RP + ks * 16) * 2;
                ldsm4(ah[mi][0], ah[mi][1], ah[mi][2], ah[mi][3], ad);
                if (TERMS == 3) ldsm4(al[mi][0], al[mi][1], al[mi][2], al[mi][3], ad + TILE_E * 2);
            }
#pragma unroll
            for (int g2 = 0; g2 < 4; ++g2) {
                const uint32_t bd = bBase + st + (uint32_t)(g2 * 16 * RP + ks * 16) * 2;
                ldsm4(bh[2 * g2][0], bh[2 * g2][1], bh[2 * g2 + 1][0], bh[2 * g2 + 1][1], bd);
                if (TERMS >= 2)
                    ldsm4(bl[2 * g2][0], bl[2 * g2][1], bl[2 * g2 + 1][0], bl[2 * g2 + 1][1],
                          bd + TILE_E * 2);
            }
#pragma unroll
            for (int mi = 0; mi < 2; ++mi)
#pragma unroll
                for (int ni = 0; ni < 8; ++ni) mma16816(acc[mi][ni], ah[mi], bh[ni]);
            if (TERMS >= 2) {
#pragma unroll
                for (int mi = 0; mi < 2; ++mi)
#pragma unroll
                    for (int ni = 0; ni < 8; ++ni) mma16816(acc[mi][ni], ah[mi], bl[ni]);
            }
            if (TERMS == 3) {
#pragma unroll
                for (int mi = 0; mi < 2; ++mi)
#pragma unroll
                    for (int ni = 0; ni < 8; ++ni) mma16816(acc[mi][ni], al[mi], bh[ni]);
            }
        }
        __syncthreads();
    }

    // ---------------- epilogue ----------------
#pragma unroll
    for (int mi = 0; mi < 2; ++mi) {
#pragma unroll
        for (int half = 0; half < 2; ++half) {
            const int row = m0 + wm * 32 + mi * 16 + (lane >> 2) + half * 8;
            float gv = 0.0f;
            if (FLAGS & F_GACC) gv = gate[row];
#pragma unroll
            for (int ni = 0; ni < 8; ++ni) {
                const int col = n0 + wn * 64 + ni * 8 + (lane & 3) * 2;
                const long long idx = z * bC + (long long)row * N + col;
                float v0 = acc[mi][ni][half * 2 + 0];
                float v1 = acc[mi][ni][half * 2 + 1];
                if (FLAGS & F_BIAS) { v0 += bias[col]; v1 += bias[col + 1]; }
                if (FLAGS & F_RELU) { v0 = fmaxf(v0, 0.0f); v1 = fmaxf(v1, 0.0f); }
                if (FLAGS & F_RES)  { v0 += res[idx]; v1 += res[idx + 1]; }
                if (FLAGS & F_GACC) {
                    float2 c = *(float2*)(C + idx);
                    c.x += gv * v0;
                    c.y += gv * v1;
                    *(float2*)(C + idx) = c;
                } else if (FLAGS & F_WF32) {
                    *(float2*)(C + idx) = make_float2(v0, v1);
                }
                if (FLAGS & F_DUP) *(float2*)(C2 + idx) = make_float2(v0, v1);
                if (FLAGS & (F_EMIT | F_EMITH)) {
                    __half h0 = __float2half(v0);
                    __half h1 = __float2half(v1);
                    *(__half2*)(Ehi + idx) = __halves2half2(h0, h1);
                    if (FLAGS & F_EMIT) {
                        __half l0 = __float2half(v0 - __half2float(h0));
                        __half l1 = __float2half(v1 - __half2float(h1));
                        *(__half2*)(Elo + idx) = __halves2half2(l0, l1);
                    }
                }
            }
        }
    }
}

// ===================== conversion kernels =====================
__global__ void convk(const float4* __restrict__ s, __half2* __restrict__ hi,
                      __half2* __restrict__ lo, int n4) {
    int i = blockIdx.x * blockDim.x + threadIdx.x;
    if (i >= n4) return;
    float4 v = s[i];
    __half h0 = __float2half(v.x), h1 = __float2half(v.y);
    __half h2 = __float2half(v.z), h3 = __float2half(v.w);
    hi[i * 2]     = __halves2half2(h0, h1);
    hi[i * 2 + 1] = __halves2half2(h2, h3);
    lo[i * 2]     = __halves2half2(__float2half(v.x - __half2float(h0)),
                                   __float2half(v.y - __half2float(h1)));
    lo[i * 2 + 1] = __halves2half2(__float2half(v.z - __half2float(h2)),
                                   __float2half(v.w - __half2float(h3)));
}

// tiled transpose + split: src f32 [R,C] -> dst fp16 [C,R] (hi, optional lo), batched
__global__ void transconv(const float* __restrict__ src, __half* __restrict__ dhi,
                          __half* __restrict__ dlo, int R, int Cn,
                          long long sS, long long sD) {
    __shared__ float t[32][33];
    const int c0 = blockIdx.x * 32, r0 = blockIdx.y * 32;
    const long long z = blockIdx.z;
    const float* s = src + z * sS;
    const int tx = threadIdx.x, ty = threadIdx.y;  // 32 x 8
#pragma unroll
    for (int i = 0; i < 4; i++)
        t[ty + i * 8][tx] = s[(long long)(r0 + ty + i * 8) * Cn + c0 + tx];
    __syncthreads();
#pragma unroll
    for (int i = 0; i < 4; i++) {
        const float v = t[tx][ty + i * 8];
        const __half h = __float2half(v);
        const long long o = z * sD + (long long)(c0 + ty + i * 8) * R + r0 + tx;
        dhi[o] = h;
        if (dlo) dlo[o] = __float2half(v - __half2float(h));
    }
}

// row softmax over 1024 cols; emits fp16 hi/lo probs
__global__ void softmax1024(const float* __restrict__ s, __half* __restrict__ phi,
                            __half* __restrict__ plo, float scale) {
    __shared__ float redm[8], reds[8];
    const long long row = blockIdx.x;
    const float4* p = reinterpret_cast<const float4*>(s + row * 1024);
    const int tid = threadIdx.x;  // 256
    float4 v = p[tid];
    v.x *= scale; v.y *= scale; v.z *= scale; v.w *= scale;
    float mx = fmaxf(fmaxf(v.x, v.y), fmaxf(v.z, v.w));
#pragma unroll
    for (int o = 16; o; o >>= 1) mx = fmaxf(mx, __shfl_xor_sync(0xffffffffu, mx, o));
    if ((tid & 31) == 0) redm[tid >> 5] = mx;
    __syncthreads();
    mx = redm[0];
#pragma unroll
    for (int i = 1; i < 8; i++) mx = fmaxf(mx, redm[i]);
    float e0 = expf(v.x - mx), e1 = expf(v.y - mx), e2 = expf(v.z - mx), e3 = expf(v.w - mx);
    float t = (e0 + e1) + (e2 + e3);
#pragma unroll
    for (int o = 16; o; o >>= 1) t += __shfl_xor_sync(0xffffffffu, t, o);
    if ((tid & 31) == 0) reds[tid >> 5] = t;
    __syncthreads();
    float sum = 0.0f;
#pragma unroll
    for (int i = 0; i < 8; i++) sum += reds[i];
    const float inv = 1.0f / sum;
    float o4[4] = {e0 * inv, e1 * inv, e2 * inv, e3 * inv};
    const long long ob = row * 1024 + tid * 4;
#pragma unroll
    for (int j2 = 0; j2 < 2; j2++) {
        __half h0 = __float2half(o4[j2 * 2]);
        __half h1 = __float2half(o4[j2 * 2 + 1]);
        ((__half2*)(phi + ob))[j2] = __halves2half2(h0, h1);
        ((__half2*)(plo + ob))[j2] =
            __halves2half2(__float2half(o4[j2 * 2] - __half2float(h0)),
                           __float2half(o4[j2 * 2 + 1] - __half2float(h1)));
    }
}

// gate logits + softmax over E=8, store [E][M]
__global__ void gates_kernel(const float* __restrict__ x1, const float* __restrict__ Wg,
                             const float* __restrict__ bg, float* __restrict__ g) {
    const int lane = threadIdx.x & 31;
    const int m = blockIdx.x * 8 + (threadIdx.x >> 5);
    const float* xr = x1 + (long long)m * 1024;
    float acc[8];
#pragma unroll
    for (int e = 0; e < 8; e++) acc[e] = 0.0f;
    for (int h0 = lane * 4; h0 < 1024; h0 += 128) {
        float4 xv = *reinterpret_cast<const float4*>(xr + h0);
        const float* wr = Wg + (long long)h0 * 8;
        float xs[4] = {xv.x, xv.y, xv.z, xv.w};
#pragma unroll
        for (int j = 0; j < 4; j++)
#pragma unroll
            for (int e = 0; e < 8; e++) acc[e] = fmaf(xs[j], wr[j * 8 + e], acc[e]);
    }
#pragma unroll
    for (int e = 0; e < 8; e++)
#pragma unroll
        for (int o = 16; o; o >>= 1) acc[e] += __shfl_xor_sync(0xffffffffu, acc[e], o);
    if (lane == 0) {
        float l[8];
        float mx = -1e30f;
#pragma unroll
        for (int e = 0; e < 8; e++) {
            l[e] = acc[e] + bg[e];
            mx = fmaxf(mx, l[e]);
        }
        float sum = 0.0f;
#pragma unroll
        for (int e = 0; e < 8; e++) {
            l[e] = expf(l[e] - mx);
            sum += l[e];
        }
        float inv = 1.0f / sum;
#pragma unroll
        for (int e = 0; e < 8; e++) g[e * 4096 + m] = l[e] * inv;
    }
}

// ===========================================================================
#define SMEM3 (2 * 4 * TILE_E * 2)  // 147456
#define SMEM1 (2 * 2 * TILE_E * 2)  // 73728

extern "C" void kernel_launch(void* const* d_in, const int* in_sizes, int n_in,
                              void* d_out, int out_size) {
    const float* x  = (const float*)d_in[0];
    const float* Wq = (const float*)d_in[1];
    const float* bq = (const float*)d_in[2];
    const float* Wk = (const float*)d_in[3];
    const float* bk = (const float*)d_in[4];
    const float* Wv = (const float*)d_in[5];
    const float* bv = (const float*)d_in[6];
    const float* Wo = (const float*)d_in[7];
    const float* bo = (const float*)d_in[8];
    const float* Wg = (const float*)d_in[9];
    const float* bg = (const float*)d_in[10];
    const float* W1 = (const float*)d_in[11];
    const float* b1 = (const float*)d_in[12];
    const float* W2 = (const float*)d_in[13];
    const float* b2 = (const float*)d_in[14];
    float* out = (float*)d_out;

    float *s, *v, *x1, *g;
    __half *hi, *lo;
    cudaGetSymbolAddress((void**)&s, g_s);
    cudaGetSymbolAddress((void**)&v, g_v);
    cudaGetSymbolAddress((void**)&x1, g_x1);
    cudaGetSymbolAddress((void**)&g, g_g);
    cudaGetSymbolAddress((void**)&hi, g_hi);
    cudaGetSymbolAddress((void**)&lo, g_lo);

    static bool attr_done = false;
    if (!attr_done) {
        cudaFuncSetAttribute(tgemm<65, 3>,  cudaFuncAttributeMaxDynamicSharedMemorySize, SMEM3);
        cudaFuncSetAttribute(tgemm<33, 3>,  cudaFuncAttributeMaxDynamicSharedMemorySize, SMEM3);
        cudaFuncSetAttribute(tgemm<32, 3>,  cudaFuncAttributeMaxDynamicSharedMemorySize, SMEM3);
        cudaFuncSetAttribute(tgemm<64, 3>,  cudaFuncAttributeMaxDynamicSharedMemorySize, SMEM3);
        cudaFuncSetAttribute(tgemm<173, 3>, cudaFuncAttributeMaxDynamicSharedMemorySize, SMEM3);
        cudaFuncSetAttribute(tgemm<131, 1>, cudaFuncAttributeMaxDynamicSharedMemorySize, SMEM1);
        cudaFuncSetAttribute(tgemm<17, 1>,  cudaFuncAttributeMaxDynamicSharedMemorySize, SMEM1);
        attr_done = true;
    }

    const long long SS = 1048576LL;  // per-batch stride (1024*1024)
    const dim3 tb(32, 8);

    // ---- conversions: x, weights (transposed to [N,K]) ----
    convk<<<4096, 256>>>((const float4*)x, (__half2*)(hi + OFF_X), (__half2*)(lo + OFF_X),
                         1048576);
    transconv<<<dim3(32, 32, 1), tb>>>(Wq, hi + OFF_WQ, lo + OFF_WQ, 1024, 1024, 0, 0);
    transconv<<<dim3(32, 32, 1), tb>>>(Wk, hi + OFF_WK, lo + OFF_WK, 1024, 1024, 0, 0);
    transconv<<<dim3(32, 32, 1), tb>>>(Wv, hi + OFF_WV, lo + OFF_WV, 1024, 1024, 0, 0);
    transconv<<<dim3(32, 32, 1), tb>>>(Wo, hi + OFF_WO, lo + OFF_WO, 1024, 1024, 0, 0);
    transconv<<<dim3(128, 32, 8), tb>>>(W1, hi + OFF_W1, nullptr, 1024, 4096,
                                        4194304, 4194304);
    transconv<<<dim3(32, 128, 8), tb>>>(W2, hi + OFF_W2, nullptr, 4096, 1024,
                                        4194304, 4194304);

    // ---- Q/K/V projections (3-term) ----
    tgemm<F_BIAS | F_EMIT, 3><<<dim3(8, 32, 1), 256, SMEM3>>>(
        hi + OFF_X, lo + OFF_X, hi + OFF_WQ, lo + OFF_WQ, bq, nullptr, nullptr, nullptr,
        nullptr, hi + OFF_Q, lo + OFF_Q, 4096, 1024, 1024, 0, 0, 0);
    tgemm<F_BIAS | F_EMIT, 3><<<dim3(8, 32, 1), 256, SMEM3>>>(
        hi + OFF_X, lo + OFF_X, hi + OFF_WK, lo + OFF_WK, bk, nullptr, nullptr, nullptr,
        nullptr, hi + OFF_K, lo + OFF_K, 4096, 1024, 1024, 0, 0, 0);
    tgemm<F_BIAS | F_WF32, 3><<<dim3(8, 32, 1), 256, SMEM3>>>(
        hi + OFF_X, lo + OFF_X, hi + OFF_WV, lo + OFF_WV, bv, nullptr, nullptr, v,
        nullptr, nullptr, nullptr, 4096, 1024, 1024, 0, 0, 0);

    // ---- scores = Q @ K^T (NT native), batched (3-term) ----
    tgemm<F_WF32, 3><<<dim3(8, 8, 4), 256, SMEM3>>>(
        hi + OFF_Q, lo + OFF_Q, hi + OFF_K, lo + OFF_K, nullptr, nullptr, nullptr, s,
        nullptr, nullptr, nullptr, 1024, 1024, 1024, SS, SS, SS);
    softmax1024<<<4096, 256>>>(s, hi + OFF_P, lo + OFF_P, 0.03125f);

    // ---- V transpose (per batch) then attn @ V (3-term) ----
    transconv<<<dim3(32, 32, 4), tb>>>(v, hi + OFF_VT, lo + OFF_VT, 1024, 1024, SS, SS);
    tgemm<F_EMIT, 3><<<dim3(8, 8, 4), 256, SMEM3>>>(
        hi + OFF_P, lo + OFF_P, hi + OFF_VT, lo + OFF_VT, nullptr, nullptr, nullptr,
        nullptr, nullptr, hi + OFF_A, lo + OFF_A, 1024, 1024, 1024, SS, SS, SS);

    // ---- x1 = x + a @ Wo + bo; dup to out; emit x1 hi (3-term) ----
    tgemm<F_BIAS | F_RES | F_WF32 | F_DUP | F_EMITH, 3><<<dim3(8, 32, 1), 256, SMEM3>>>(
        hi + OFF_A, lo + OFF_A, hi + OFF_WO, lo + OFF_WO, bo, nullptr, x, x1, out,
        hi + OFF_X1, nullptr, 4096, 1024, 1024, 0, 0, 0);

    // ---- gates ----
    gates_kernel<<<512, 256>>>(x1, Wg, bg, g);

    // ---- MoE (1-term fp16): out += gate_e * (relu(x1 @ W1[e] + b1) @ W2[e] + b2) ----
    for (int e = 0; e < 8; e++) {
        tgemm<F_BIAS | F_RELU | F_EMITH, 1><<<dim3(32, 32, 1), 256, SMEM1>>>(
            hi + OFF_X1, nullptr, hi + OFF_W1 + (long long)e * 4194304, nullptr,
            b1 + e * 4096, nullptr, nullptr, nullptr, nullptr, hi + OFF_H, nullptr,
            4096, 4096, 1024, 0, 0, 0);
        tgemm<F_BIAS | F_GACC, 1><<<dim3(8, 32, 1), 256, SMEM1>>>(
            hi + OFF_H, nullptr, hi + OFF_W2 + (long long)e * 4194304, nullptr,
            b2 + e * 1024, g + e * 4096, nullptr, out, nullptr, nullptr, nullptr,
            4096, 1024, 4096, 0, 0, 0);
    }
}

// round 12
// speedup vs baseline: 1.1822x; 1.1822x over previous
#include <cuda_runtime.h>
#include <cuda_fp16.h>
#include <cstdint>

// ===================== scratch (device globals; allocation-free) =====================
__device__ float g_s [4194304];   // [4,1024,1024] raw scores
__device__ float g_v [4194304];   // [4096,1024] V (fp32, pre-transpose)
__device__ float g_x1[4194304];   // x + attn proj (fp32, for gates + residual)
__device__ float g_g [32768];     // gates [E][4096]

// fp16 hi/lo pools (split-precision operands), element offsets below
#define OFF_X   0LL
#define OFF_Q   4194304LL
#define OFF_K   8388608LL
#define OFF_VT  12582912LL
#define OFF_P   16777216LL
#define OFF_A   20971520LL
#define OFF_X1  25165824LL
#define OFF_H   29360128LL
#define OFF_WQ  46137344LL
#define OFF_WK  47185920LL
#define OFF_WV  48234496LL
#define OFF_WO  49283072LL
#define OFF_W1  50331648LL
#define OFF_W2  83886080LL
#define POOL_SZ 117440512LL
__device__ __half g_hi[POOL_SZ];
__device__ __half g_lo[POOL_SZ];

// ===================== PTX helpers (sm_80+ only) =====================
__device__ __forceinline__ uint32_t s2u(const void* p) {
    uint32_t a;
    asm("{ .reg .u64 t; cvta.to.shared.u64 t, %1; cvt.u32.u64 %0, t; }" : "=r"(a) : "l"(p));
    return a;
}
__device__ __forceinline__ void ldsm4(uint32_t& r0, uint32_t& r1, uint32_t& r2, uint32_t& r3,
                                      uint32_t addr) {
    asm volatile("ldmatrix.sync.aligned.m8n8.x4.shared.b16 {%0,%1,%2,%3}, [%4];"
                 : "=r"(r0), "=r"(r1), "=r"(r2), "=r"(r3) : "r"(addr));
}
__device__ __forceinline__ void mma16816(float* d, const uint32_t* a, const uint32_t* b) {
    asm volatile(
        "mma.sync.aligned.m16n8k16.row.col.f32.f16.f16.f32 "
        "{%0,%1,%2,%3}, {%4,%5,%6,%7}, {%8,%9}, {%0,%1,%2,%3};"
        : "+f"(d[0]), "+f"(d[1]), "+f"(d[2]), "+f"(d[3])
        : "r"(a[0]), "r"(a[1]), "r"(a[2]), "r"(a[3]), "r"(b[0]), "r"(b[1]));
}
__device__ __forceinline__ void cpasync16(uint32_t saddr, const void* g) {
    asm volatile("cp.async.cg.shared.global [%0], [%1], 16;" :: "r"(saddr), "l"(g));
}
#define CP_COMMIT() asm volatile("cp.async.commit_group;" ::: "memory")
#define CP_WAIT0()  asm volatile("cp.async.wait_group 0;" ::: "memory")

// ===================== split-fp16 warp-MMA GEMM =====================
// Tile 128x128, K-chunk 64, double-buffered cp.async, 256 threads (8 warps 4m x 2n).
// TERMS==3: D = Ah*Bh + Ah*Bl + Al*Bh   (near-fp32)
// TERMS==2: D = Ah*Bh + Ah*Bl           (A unsplit fp16; err ~2^-11 pre-aggregation)
#define KT 64
#define RP 72                    // padded row length (elements)
#define TILE_E (128 * RP)        // 9216 elems per operand tile

#define F_BIAS  1
#define F_RELU  2
#define F_RES   4
#define F_DUP   8
#define F_GACC  16
#define F_WF32  32
#define F_EMIT  64
#define F_EMITH 128

template <int FLAGS, int TERMS>
__global__ void __launch_bounds__(256, 1)
tgemm(const __half* __restrict__ Ahi, const __half* __restrict__ Alo,
      const __half* __restrict__ Bhi, const __half* __restrict__ Blo,
      const float* __restrict__ bias, const float* __restrict__ gate,
      const float* __restrict__ res, float* __restrict__ C, float* __restrict__ C2,
      __half* __restrict__ Ehi, __half* __restrict__ Elo,
      int M, int N, int K, long long bA, long long bB, long long bC) {
    constexpr int NTILES = TERMS + 1;  // 3:Ah,Al,Bh,Bl  2:Ah,Bh,Bl
    constexpr uint32_t STAGE_B = NTILES * TILE_E * 2;
    constexpr uint32_t BH_OFF = (TERMS == 3 ? 2 : 1) * TILE_E * 2;

    extern __shared__ __half sm[];
    const int tid = threadIdx.x, lane = tid & 31, wid = tid >> 5;
    const int wm = wid >> 1, wn = wid & 1;
    const long long z = blockIdx.z;
    const int m0 = blockIdx.y * 128, n0 = blockIdx.x * 128;
    const __half* Ah = Ahi + z * bA + (long long)m0 * K;
    const __half* Al = (TERMS == 3) ? (Alo + z * bA + (long long)m0 * K) : nullptr;
    const __half* Bh = Bhi + z * bB + (long long)n0 * K;
    const __half* Bl = Blo + z * bB + (long long)n0 * K;
    const uint32_t sbase = s2u(sm);

    // loader mapping: thread -> (row, 32-elem half-row)
    const int lr = tid >> 1;
    const int lc0 = (tid & 1) * 32;
    const long long gro = (long long)lr * K + lc0;
    const uint32_t sro = (uint32_t)lr * RP * 2 + (uint32_t)lc0 * 2;

    auto load_stage = [&](int kt, int s) {
        const long long go = gro + (long long)kt * KT;
        const uint32_t sd = sbase + (uint32_t)s * STAGE_B + sro;
#pragma unroll
        for (int j = 0; j < 4; ++j) {
            cpasync16(sd + j * 16, Ah + go + j * 8);
            if (TERMS == 3) cpasync16(sd + TILE_E * 2 + j * 16, Al + go + j * 8);
            cpasync16(sd + BH_OFF + j * 16, Bh + go + j * 8);
            cpasync16(sd + BH_OFF + TILE_E * 2 + j * 16, Bl + go + j * 8);
        }
    };

    // ldmatrix per-lane base addresses (byte offsets into a stage)
    const uint32_t aBase =
        sbase + ((uint32_t)(wm * 32 + (lane & 7) + ((lane >> 3) & 1) * 8) * RP +
                 ((lane >> 4) & 1) * 8) * 2;
    const uint32_t bBase =
        sbase + BH_OFF +
        ((uint32_t)(wn * 64 + (lane >> 4) * 8 + (lane & 7)) * RP + ((lane >> 3) & 1) * 8) * 2;

    float acc[2][8][4];
#pragma unroll
    for (int i = 0; i < 2; i++)
#pragma unroll
        for (int j = 0; j < 8; j++)
#pragma unroll
            for (int q = 0; q < 4; q++) acc[i][j][q] = 0.0f;

    load_stage(0, 0);
    CP_COMMIT();

    const int nk = K >> 6;
    for (int kt = 0; kt < nk; ++kt) {
        const int b = kt & 1;
        CP_WAIT0();
        __syncthreads();
        if (kt + 1 < nk) {
            load_stage(kt + 1, b ^ 1);
            CP_COMMIT();
        }
        const uint32_t st = (uint32_t)b * STAGE_B;
#pragma unroll
        for (int ks = 0; ks < 4; ++ks) {
            uint32_t ah[2][4], al[2][4], bh[8][2], bl[8][2];
#pragma unroll
            for (int mi = 0; mi < 2; ++mi) {
                const uint32_t ad = aBase + st + (uint32_t)(mi * 16 * RP + ks * 16) * 2;
                ldsm4(ah[mi][0], ah[mi][1], ah[mi][2], ah[mi][3], ad);
                if (TERMS == 3) ldsm4(al[mi][0], al[mi][1], al[mi][2], al[mi][3], ad + TILE_E * 2);
            }
#pragma unroll
            for (int g2 = 0; g2 < 4; ++g2) {
                const uint32_t bd = bBase + st + (uint32_t)(g2 * 16 * RP + ks * 16) * 2;
                ldsm4(bh[2 * g2][0], bh[2 * g2][1], bh[2 * g2 + 1][0], bh[2 * g2 + 1][1], bd);
                ldsm4(bl[2 * g2][0], bl[2 * g2][1], bl[2 * g2 + 1][0], bl[2 * g2 + 1][1],
                      bd + TILE_E * 2);
            }
#pragma unroll
            for (int mi = 0; mi < 2; ++mi)
#pragma unroll
                for (int ni = 0; ni < 8; ++ni) mma16816(acc[mi][ni], ah[mi], bh[ni]);
#pragma unroll
            for (int mi = 0; mi < 2; ++mi)
#pragma unroll
                for (int ni = 0; ni < 8; ++ni) mma16816(acc[mi][ni], ah[mi], bl[ni]);
            if (TERMS == 3) {
#pragma unroll
                for (int mi = 0; mi < 2; ++mi)
#pragma unroll
                    for (int ni = 0; ni < 8; ++ni) mma16816(acc[mi][ni], al[mi], bh[ni]);
            }
        }
        __syncthreads();
    }

    // ---------------- epilogue ----------------
#pragma unroll
    for (int mi = 0; mi < 2; ++mi) {
#pragma unroll
        for (int half = 0; half < 2; ++half) {
            const int row = m0 + wm * 32 + mi * 16 + (lane >> 2) + half * 8;
            float gv = 0.0f;
            if (FLAGS & F_GACC) gv = gate[row];
#pragma unroll
            for (int ni = 0; ni < 8; ++ni) {
                const int col = n0 + wn * 64 + ni * 8 + (lane & 3) * 2;
                const long long idx = z * bC + (long long)row * N + col;
                float v0 = acc[mi][ni][half * 2 + 0];
                float v1 = acc[mi][ni][half * 2 + 1];
                if (FLAGS & F_BIAS) { v0 += bias[col]; v1 += bias[col + 1]; }
                if (FLAGS & F_RELU) { v0 = fmaxf(v0, 0.0f); v1 = fmaxf(v1, 0.0f); }
                if (FLAGS & F_RES)  { v0 += res[idx]; v1 += res[idx + 1]; }
                if (FLAGS & F_GACC) {
                    float2 c = *(float2*)(C + idx);
                    c.x += gv * v0;
                    c.y += gv * v1;
                    *(float2*)(C + idx) = c;
                } else if (FLAGS & F_WF32) {
                    *(float2*)(C + idx) = make_float2(v0, v1);
                }
                if (FLAGS & F_DUP) *(float2*)(C2 + idx) = make_float2(v0, v1);
                if (FLAGS & (F_EMIT | F_EMITH)) {
                    __half h0 = __float2half(v0);
                    __half h1 = __float2half(v1);
                    *(__half2*)(Ehi + idx) = __halves2half2(h0, h1);
                    if (FLAGS & F_EMIT) {
                        __half l0 = __float2half(v0 - __half2float(h0));
                        __half l1 = __float2half(v1 - __half2float(h1));
                        *(__half2*)(Elo + idx) = __halves2half2(l0, l1);
                    }
                }
            }
        }
    }
}

// ===================== conversion kernels =====================
__global__ void convk(const float4* __restrict__ s, __half2* __restrict__ hi,
                      __half2* __restrict__ lo, int n4) {
    int i = blockIdx.x * blockDim.x + threadIdx.x;
    if (i >= n4) return;
    float4 v = s[i];
    __half h0 = __float2half(v.x), h1 = __float2half(v.y);
    __half h2 = __float2half(v.z), h3 = __float2half(v.w);
    hi[i * 2]     = __halves2half2(h0, h1);
    hi[i * 2 + 1] = __halves2half2(h2, h3);
    if (lo) {
        lo[i * 2]     = __halves2half2(__float2half(v.x - __half2float(h0)),
                                       __float2half(v.y - __half2float(h1)));
        lo[i * 2 + 1] = __halves2half2(__float2half(v.z - __half2float(h2)),
                                       __float2half(v.w - __half2float(h3)));
    }
}

// tiled transpose + split: src f32 [R,C] -> dst fp16 [C,R] (hi, optional lo), batched
__global__ void transconv(const float* __restrict__ src, __half* __restrict__ dhi,
                          __half* __restrict__ dlo, int R, int Cn,
                          long long sS, long long sD) {
    __shared__ float t[32][33];
    const int c0 = blockIdx.x * 32, r0 = blockIdx.y * 32;
    const long long z = blockIdx.z;
    const float* s = src + z * sS;
    const int tx = threadIdx.x, ty = threadIdx.y;  // 32 x 8
#pragma unroll
    for (int i = 0; i < 4; i++)
        t[ty + i * 8][tx] = s[(long long)(r0 + ty + i * 8) * Cn + c0 + tx];
    __syncthreads();
#pragma unroll
    for (int i = 0; i < 4; i++) {
        const float v = t[tx][ty + i * 8];
        const __half h = __float2half(v);
        const long long o = z * sD + (long long)(c0 + ty + i * 8) * R + r0 + tx;
        dhi[o] = h;
        if (dlo) dlo[o] = __float2half(v - __half2float(h));
    }
}

// row softmax over 1024 cols; emits fp16 hi/lo probs
__global__ void softmax1024(const float* __restrict__ s, __half* __restrict__ phi,
                            __half* __restrict__ plo, float scale) {
    __shared__ float redm[8], reds[8];
    const long long row = blockIdx.x;
    const float4* p = reinterpret_cast<const float4*>(s + row * 1024);
    const int tid = threadIdx.x;  // 256
    float4 v = p[tid];
    v.x *= scale; v.y *= scale; v.z *= scale; v.w *= scale;
    float mx = fmaxf(fmaxf(v.x, v.y), fmaxf(v.z, v.w));
#pragma unroll
    for (int o = 16; o; o >>= 1) mx = fmaxf(mx, __shfl_xor_sync(0xffffffffu, mx, o));
    if ((tid & 31) == 0) redm[tid >> 5] = mx;
    __syncthreads();
    mx = redm[0];
#pragma unroll
    for (int i = 1; i < 8; i++) mx = fmaxf(mx, redm[i]);
    float e0 = expf(v.x - mx), e1 = expf(v.y - mx), e2 = expf(v.z - mx), e3 = expf(v.w - mx);
    float t = (e0 + e1) + (e2 + e3);
#pragma unroll
    for (int o = 16; o; o >>= 1) t += __shfl_xor_sync(0xffffffffu, t, o);
    if ((tid & 31) == 0) reds[tid >> 5] = t;
    __syncthreads();
    float sum = 0.0f;
#pragma unroll
    for (int i = 0; i < 8; i++) sum += reds[i];
    const float inv = 1.0f / sum;
    float o4[4] = {e0 * inv, e1 * inv, e2 * inv, e3 * inv};
    const long long ob = row * 1024 + tid * 4;
#pragma unroll
    for (int j2 = 0; j2 < 2; j2++) {
        __half h0 = __float2half(o4[j2 * 2]);
        __half h1 = __float2half(o4[j2 * 2 + 1]);
        ((__half2*)(phi + ob))[j2] = __halves2half2(h0, h1);
        ((__half2*)(plo + ob))[j2] =
            __halves2half2(__float2half(o4[j2 * 2] - __half2float(h0)),
                           __float2half(o4[j2 * 2 + 1] - __half2float(h1)));
    }
}

// gate logits + softmax over E=8, store [E][M]
__global__ void gates_kernel(const float* __restrict__ x1, const float* __restrict__ Wg,
                             const float* __restrict__ bg, float* __restrict__ g) {
    const int lane = threadIdx.x & 31;
    const int m = blockIdx.x * 8 + (threadIdx.x >> 5);
    const float* xr = x1 + (long long)m * 1024;
    float acc[8];
#pragma unroll
    for (int e = 0; e < 8; e++) acc[e] = 0.0f;
    for (int h0 = lane * 4; h0 < 1024; h0 += 128) {
        float4 xv = *reinterpret_cast<const float4*>(xr + h0);
        const float* wr = Wg + (long long)h0 * 8;
        float xs[4] = {xv.x, xv.y, xv.z, xv.w};
#pragma unroll
        for (int j = 0; j < 4; j++)
#pragma unroll
            for (int e = 0; e < 8; e++) acc[e] = fmaf(xs[j], wr[j * 8 + e], acc[e]);
    }
#pragma unroll
    for (int e = 0; e < 8; e++)
#pragma unroll
        for (int o = 16; o; o >>= 1) acc[e] += __shfl_xor_sync(0xffffffffu, acc[e], o);
    if (lane == 0) {
        float l[8];
        float mx = -1e30f;
#pragma unroll
        for (int e = 0; e < 8; e++) {
            l[e] = acc[e] + bg[e];
            mx = fmaxf(mx, l[e]);
        }
        float sum = 0.0f;
#pragma unroll
        for (int e = 0; e < 8; e++) {
            l[e] = expf(l[e] - mx);
            sum += l[e];
        }
        float inv = 1.0f / sum;
#pragma unroll
        for (int e = 0; e < 8; e++) g[e * 4096 + m] = l[e] * inv;
    }
}

// ===========================================================================
#define SMEM3 (2 * 4 * TILE_E * 2)  // 147456
#define SMEM2 (2 * 3 * TILE_E * 2)  // 110592

extern "C" void kernel_launch(void* const* d_in, const int* in_sizes, int n_in,
                              void* d_out, int out_size) {
    const float* x  = (const float*)d_in[0];
    const float* Wq = (const float*)d_in[1];
    const float* bq = (const float*)d_in[2];
    const float* Wk = (const float*)d_in[3];
    const float* bk = (const float*)d_in[4];
    const float* Wv = (const float*)d_in[5];
    const float* bv = (const float*)d_in[6];
    const float* Wo = (const float*)d_in[7];
    const float* bo = (const float*)d_in[8];
    const float* Wg = (const float*)d_in[9];
    const float* bg = (const float*)d_in[10];
    const float* W1 = (const float*)d_in[11];
    const float* b1 = (const float*)d_in[12];
    const float* W2 = (const float*)d_in[13];
    const float* b2 = (const float*)d_in[14];
    float* out = (float*)d_out;

    float *s, *v, *x1, *g;
    __half *hi, *lo;
    cudaGetSymbolAddress((void**)&s, g_s);
    cudaGetSymbolAddress((void**)&v, g_v);
    cudaGetSymbolAddress((void**)&x1, g_x1);
    cudaGetSymbolAddress((void**)&g, g_g);
    cudaGetSymbolAddress((void**)&hi, g_hi);
    cudaGetSymbolAddress((void**)&lo, g_lo);

    static bool attr_done = false;
    if (!attr_done) {
        cudaFuncSetAttribute(tgemm<F_BIAS | F_EMIT, 2>,
                             cudaFuncAttributeMaxDynamicSharedMemorySize, SMEM2);
        cudaFuncSetAttribute(tgemm<F_BIAS | F_WF32, 2>,
                             cudaFuncAttributeMaxDynamicSharedMemorySize, SMEM2);
        cudaFuncSetAttribute(tgemm<F_WF32, 3>,
                             cudaFuncAttributeMaxDynamicSharedMemorySize, SMEM3);
        cudaFuncSetAttribute(tgemm<F_EMITH, 3>,
                             cudaFuncAttributeMaxDynamicSharedMemorySize, SMEM3);
        cudaFuncSetAttribute(tgemm<F_BIAS | F_RES | F_WF32 | F_DUP | F_EMITH, 2>,
                             cudaFuncAttributeMaxDynamicSharedMemorySize, SMEM2);
        cudaFuncSetAttribute(tgemm<F_BIAS | F_RELU | F_EMITH, 2>,
                             cudaFuncAttributeMaxDynamicSharedMemorySize, SMEM2);
        cudaFuncSetAttribute(tgemm<F_BIAS | F_GACC, 2>,
                             cudaFuncAttributeMaxDynamicSharedMemorySize, SMEM2);
        attr_done = true;
    }

    const long long SS = 1048576LL;  // per-batch stride (1024*1024)
    const dim3 tb(32, 8);

    // ---- conversions: x (hi only — projections are 2-term), weights (transposed) ----
    convk<<<4096, 256>>>((const float4*)x, (__half2*)(hi + OFF_X), nullptr, 1048576);
    transconv<<<dim3(32, 32, 1), tb>>>(Wq, hi + OFF_WQ, lo + OFF_WQ, 1024, 1024, 0, 0);
    transconv<<<dim3(32, 32, 1), tb>>>(Wk, hi + OFF_WK, lo + OFF_WK, 1024, 1024, 0, 0);
    transconv<<<dim3(32, 32, 1), tb>>>(Wv, hi + OFF_WV, lo + OFF_WV, 1024, 1024, 0, 0);
    transconv<<<dim3(32, 32, 1), tb>>>(Wo, hi + OFF_WO, lo + OFF_WO, 1024, 1024, 0, 0);
    transconv<<<dim3(128, 32, 8), tb>>>(W1, hi + OFF_W1, lo + OFF_W1, 1024, 4096,
                                        4194304, 4194304);
    transconv<<<dim3(32, 128, 8), tb>>>(W2, hi + OFF_W2, lo + OFF_W2, 4096, 1024,
                                        4194304, 4194304);

    // ---- Q/K/V projections (2-term: A = x hi, B = W hi/lo) ----
    tgemm<F_BIAS | F_EMIT, 2><<<dim3(8, 32, 1), 256, SMEM2>>>(
        hi + OFF_X, nullptr, hi + OFF_WQ, lo + OFF_WQ, bq, nullptr, nullptr, nullptr,
        nullptr, hi + OFF_Q, lo + OFF_Q, 4096, 1024, 1024, 0, 0, 0);
    tgemm<F_BIAS | F_EMIT, 2><<<dim3(8, 32, 1), 256, SMEM2>>>(
        hi + OFF_X, nullptr, hi + OFF_WK, lo + OFF_WK, bk, nullptr, nullptr, nullptr,
        nullptr, hi + OFF_K, lo + OFF_K, 4096, 1024, 1024, 0, 0, 0);
    tgemm<F_BIAS | F_WF32, 2><<<dim3(8, 32, 1), 256, SMEM2>>>(
        hi + OFF_X, nullptr, hi + OFF_WV, lo + OFF_WV, bv, nullptr, nullptr, v,
        nullptr, nullptr, nullptr, 4096, 1024, 1024, 0, 0, 0);

    // ---- scores = Q @ K^T (NT native), batched (3-term) ----
    tgemm<F_WF32, 3><<<dim3(8, 8, 4), 256, SMEM3>>>(
        hi + OFF_Q, lo + OFF_Q, hi + OFF_K, lo + OFF_K, nullptr, nullptr, nullptr, s,
        nullptr, nullptr, nullptr, 1024, 1024, 1024, SS, SS, SS);
    softmax1024<<<4096, 256>>>(s, hi + OFF_P, lo + OFF_P, 0.03125f);

    // ---- V transpose (per batch) then attn @ V (3-term; emit a hi only) ----
    transconv<<<dim3(32, 32, 4), tb>>>(v, hi + OFF_VT, lo + OFF_VT, 1024, 1024, SS, SS);
    tgemm<F_EMITH, 3><<<dim3(8, 8, 4), 256, SMEM3>>>(
        hi + OFF_P, lo + OFF_P, hi + OFF_VT, lo + OFF_VT, nullptr, nullptr, nullptr,
        nullptr, nullptr, hi + OFF_A, nullptr, 1024, 1024, 1024, SS, SS, SS);

    // ---- x1 = x + a @ Wo + bo; dup to out; emit x1 hi (2-term) ----
    tgemm<F_BIAS | F_RES | F_WF32 | F_DUP | F_EMITH, 2><<<dim3(8, 32, 1), 256, SMEM2>>>(
        hi + OFF_A, nullptr, hi + OFF_WO, lo + OFF_WO, bo, nullptr, x, x1, out,
        hi + OFF_X1, nullptr, 4096, 1024, 1024, 0, 0, 0);

    // ---- gates ----
    gates_kernel<<<512, 256>>>(x1, Wg, bg, g);

    // ---- MoE (2-term): out += gate_e * (relu(x1 @ W1[e] + b1) @ W2[e] + b2) ----
    for (int e = 0; e < 8; e++) {
        tgemm<F_BIAS | F_RELU | F_EMITH, 2><<<dim3(32, 32, 1), 256, SMEM2>>>(
            hi + OFF_X1, nullptr, hi + OFF_W1 + (long long)e * 4194304,
            lo + OFF_W1 + (long long)e * 4194304, b1 + e * 4096, nullptr, nullptr,
            nullptr, nullptr, hi + OFF_H, nullptr, 4096, 4096, 1024, 0, 0, 0);
        tgemm<F_BIAS | F_GACC, 2><<<dim3(8, 32, 1), 256, SMEM2>>>(
            hi + OFF_H, nullptr, hi + OFF_W2 + (long long)e * 4194304,
            lo + OFF_W2 + (long long)e * 4194304, b2 + e * 1024, g + e * 4096, nullptr,
            out, nullptr, nullptr, nullptr, 4096, 1024, 4096, 0, 0, 0);
    }
}